// round 10
// baseline (speedup 1.0000x reference)
#include <cuda_runtime.h>
#include <cuda_bf16.h>
#include <cstdint>
#include <math.h>

#define S_LEN   4096
#define DMODEL  1024
#define NHEADS  16
#define DK      64

// ---------------- scratch (__device__ globals: allocation-free) ------------
__device__ __nv_bfloat16 g_xhi[S_LEN * DMODEL];   // x hi; later reused: attn-out hi
__device__ __nv_bfloat16 g_xlo[S_LEN * DMODEL];   // x lo; later reused: attn-out lo
__device__ __nv_bfloat16 g_qhi[S_LEN * DMODEL];
__device__ __nv_bfloat16 g_qlo[S_LEN * DMODEL];
__device__ __nv_bfloat16 g_khi[S_LEN * DMODEL];
__device__ __nv_bfloat16 g_klo[S_LEN * DMODEL];
__device__ __nv_bfloat16 g_vhi[S_LEN * DMODEL];
__device__ __nv_bfloat16 g_vlo[S_LEN * DMODEL];
__device__ __nv_bfloat16 g_wqhi[DMODEL * DMODEL];
__device__ __nv_bfloat16 g_wqlo[DMODEL * DMODEL];
__device__ __nv_bfloat16 g_wkhi[DMODEL * DMODEL];
__device__ __nv_bfloat16 g_wklo[DMODEL * DMODEL];
__device__ __nv_bfloat16 g_wvhi[DMODEL * DMODEL];
__device__ __nv_bfloat16 g_wvlo[DMODEL * DMODEL];
__device__ __nv_bfloat16 g_wohi[DMODEL * DMODEL];
__device__ __nv_bfloat16 g_wolo[DMODEL * DMODEL];

// ---------------------------------------------------------------------------
// helpers
// ---------------------------------------------------------------------------
__device__ __forceinline__ void split_store(const float4 v,
    __nv_bfloat16* hi, __nv_bfloat16* lo, int i)
{
    __nv_bfloat16 h0 = __float2bfloat16(v.x);
    __nv_bfloat16 h1 = __float2bfloat16(v.y);
    __nv_bfloat16 h2 = __float2bfloat16(v.z);
    __nv_bfloat16 h3 = __float2bfloat16(v.w);
    __nv_bfloat16 l0 = __float2bfloat16(v.x - __bfloat162float(h0));
    __nv_bfloat16 l1 = __float2bfloat16(v.y - __bfloat162float(h1));
    __nv_bfloat16 l2 = __float2bfloat16(v.z - __bfloat162float(h2));
    __nv_bfloat16 l3 = __float2bfloat16(v.w - __bfloat162float(h3));
    ((__nv_bfloat162*)hi)[2 * i + 0] = __nv_bfloat162(h0, h1);
    ((__nv_bfloat162*)hi)[2 * i + 1] = __nv_bfloat162(h2, h3);
    ((__nv_bfloat162*)lo)[2 * i + 0] = __nv_bfloat162(l0, l1);
    ((__nv_bfloat162*)lo)[2 * i + 1] = __nv_bfloat162(l2, l3);
}

__global__ __launch_bounds__(256) void cvt_split_kernel(
    const float* __restrict__ src,
    __nv_bfloat16* __restrict__ hi, __nv_bfloat16* __restrict__ lo, int n4)
{
    int i = blockIdx.x * 256 + threadIdx.x;
    if (i >= n4) return;
    split_store(((const float4*)src)[i], hi, lo, i);
}

// batched: 4 weight matrices in one launch (blockIdx.y selects matrix)
__global__ __launch_bounds__(256) void cvt_split4_kernel(
    const float* s0, const float* s1, const float* s2, const float* s3,
    __nv_bfloat16* h0, __nv_bfloat16* h1, __nv_bfloat16* h2, __nv_bfloat16* h3,
    __nv_bfloat16* l0, __nv_bfloat16* l1, __nv_bfloat16* l2, __nv_bfloat16* l3,
    int n4)
{
    int i = blockIdx.x * 256 + threadIdx.x;
    if (i >= n4) return;
    const float* src;
    __nv_bfloat16 *hi, *lo;
    switch (blockIdx.y) {
        case 0: src = s0; hi = h0; lo = l0; break;
        case 1: src = s1; hi = h1; lo = l1; break;
        case 2: src = s2; hi = h2; lo = l2; break;
        default: src = s3; hi = h3; lo = l3; break;
    }
    split_store(((const float4*)src)[i], hi, lo, i);
}

__device__ __forceinline__ void mma16816(float* c, const uint32_t* a,
                                         uint32_t b0, uint32_t b1) {
    asm volatile(
        "mma.sync.aligned.m16n8k16.row.col.f32.bf16.bf16.f32 "
        "{%0,%1,%2,%3}, {%4,%5,%6,%7}, {%8,%9}, {%0,%1,%2,%3};\n"
        : "+f"(c[0]), "+f"(c[1]), "+f"(c[2]), "+f"(c[3])
        : "r"(a[0]), "r"(a[1]), "r"(a[2]), "r"(a[3]), "r"(b0), "r"(b1));
}

__device__ __forceinline__ void ldm_x4(uint32_t* r, uint32_t addr) {
    asm volatile("ldmatrix.sync.aligned.m8n8.x4.shared.b16 {%0,%1,%2,%3}, [%4];"
        : "=r"(r[0]), "=r"(r[1]), "=r"(r[2]), "=r"(r[3]) : "r"(addr));
}

__device__ __forceinline__ void ldm_x4_t(uint32_t* r, uint32_t addr) {
    asm volatile("ldmatrix.sync.aligned.m8n8.x4.trans.shared.b16 {%0,%1,%2,%3}, [%4];"
        : "=r"(r[0]), "=r"(r[1]), "=r"(r[2]), "=r"(r[3]) : "r"(addr));
}

__device__ __forceinline__ void split2(float x, float y, uint32_t& hi, uint32_t& lo) {
    __nv_bfloat16 hx = __float2bfloat16(x), hy = __float2bfloat16(y);
    __nv_bfloat16 lx = __float2bfloat16(x - __bfloat162float(hx));
    __nv_bfloat16 ly = __float2bfloat16(y - __bfloat162float(hy));
    __nv_bfloat162 h(hx, hy), l(lx, ly);
    hi = *(uint32_t*)&h; lo = *(uint32_t*)&l;
}

// ---------------------------------------------------------------------------
// bf16-split HMMA GEMM: C = (Ahi+Alo)[M,K] @ (Bhi+Blo)[N,K]^T + bias
// CTA 128x128, BK=32, 8 warps (32x64). 2 CTAs/SM (80KB smem) -> grid fits
// in ONE wave. Issue-before-compute, one __syncthreads per K-iter.
// ---------------------------------------------------------------------------
#define GBK      32
#define ROW_B    80                // 64B data + 16B pad
#define TILE_B   (128 * ROW_B)     // 10240
#define STAGE_B  (4 * TILE_B)      // 40960
#define GEMM_SMEM (2 * STAGE_B)    // 81920

__global__ __launch_bounds__(256, 2) void gemm_mma_kernel(
    const __nv_bfloat16* __restrict__ Ahi, const __nv_bfloat16* __restrict__ Alo,
    const __nv_bfloat16* __restrict__ Bhi, const __nv_bfloat16* __restrict__ Blo,
    const float* __restrict__ bias, float* __restrict__ Cf,
    __nv_bfloat16* __restrict__ Chi, __nv_bfloat16* __restrict__ Clo, int K)
{
    extern __shared__ char sm_raw[];
    int tid  = threadIdx.x;
    int lane = tid & 31, wid = tid >> 5;
    int g = lane >> 2;
    int q = lane & 3;
    int warpM = (wid & 3) * 32;
    int warpN = (wid >> 2) * 64;
    int n0 = blockIdx.x * 128;
    int m0 = blockIdx.y * 128;

    uint32_t sbase = (uint32_t)__cvta_generic_to_shared(sm_raw);

    float acc[2][8][4] = {};
    const __nv_bfloat16* srcs[4] = {Ahi, Alo, Bhi, Blo};

    // 4 tiles of [128][32] bf16 (64B rows), 16B chunks, 512 chunks/tile
    auto issue_loads = [&](int stage, int k0) {
        uint32_t st = sbase + stage * STAGE_B;
        int row4 = tid >> 2;      // 0..63
        int ch   = tid & 3;
        #pragma unroll
        for (int t = 0; t < 4; t++) {
            int rbase = (t < 2) ? m0 : n0;
            #pragma unroll
            for (int h = 0; h < 2; h++) {
                int row = row4 + h * 64;
                const void* gp = srcs[t] + (size_t)(rbase + row) * K + k0 + ch * 8;
                uint32_t dp = st + t * TILE_B + row * ROW_B + ch * 16;
                asm volatile("cp.async.cg.shared.global [%0], [%1], 16;\n"
                             :: "r"(dp), "l"(gp));
            }
        }
        asm volatile("cp.async.commit_group;\n" ::: "memory");
    };

    auto compute = [&](int stage) {
        uint32_t st = sbase + stage * STAGE_B;
        uint32_t sA = st;               // Ahi; Alo at +TILE_B
        uint32_t sB = st + 2 * TILE_B;  // Bhi; Blo at +TILE_B
        int grp = lane >> 3;
        #pragma unroll
        for (int ks = 0; ks < GBK; ks += 16) {
            uint32_t ah[2][4], al[2][4];
            #pragma unroll
            for (int i = 0; i < 2; i++) {
                uint32_t ad = sA + (uint32_t)((warpM + i * 16 + (lane & 15)) * ROW_B
                                              + (ks + (lane >> 4) * 8) * 2);
                ldm_x4(ah[i], ad);
                ldm_x4(al[i], ad + TILE_B);
            }
            #pragma unroll
            for (int jp = 0; jp < 4; jp++) {
                uint32_t bd = sB + (uint32_t)((warpN + (jp * 2 + (grp >> 1)) * 8 + (lane & 7)) * ROW_B
                                              + (ks + (grp & 1) * 8) * 2);
                uint32_t bh[4], bl[4];
                ldm_x4(bh, bd);
                ldm_x4(bl, bd + TILE_B);
                #pragma unroll
                for (int i = 0; i < 2; i++) {
                    mma16816(acc[i][jp * 2],     ah[i], bh[0], bh[1]);
                    mma16816(acc[i][jp * 2],     ah[i], bl[0], bl[1]);
                    mma16816(acc[i][jp * 2],     al[i], bh[0], bh[1]);
                    mma16816(acc[i][jp * 2 + 1], ah[i], bh[2], bh[3]);
                    mma16816(acc[i][jp * 2 + 1], ah[i], bl[2], bl[3]);
                    mma16816(acc[i][jp * 2 + 1], al[i], bh[2], bh[3]);
                }
            }
        }
    };

    const int NITER = K / GBK;    // 32
    issue_loads(0, 0);
    asm volatile("cp.async.wait_group 0;\n" ::: "memory");
    __syncthreads();
    for (int it = 0; it < NITER; it++) {
        if (it + 1 < NITER) issue_loads((it + 1) & 1, (it + 1) * GBK);
        compute(it & 1);
        if (it + 1 < NITER) {
            asm volatile("cp.async.wait_group 0;\n" ::: "memory");
            __syncthreads();
        }
    }

    // --- epilogue ---
    #pragma unroll
    for (int i = 0; i < 2; i++) {
        int r0 = m0 + warpM + i * 16 + g;
        #pragma unroll
        for (int j = 0; j < 8; j++) {
            int c = n0 + warpN + j * 8 + q * 2;
            float2 b2 = *(const float2*)(bias + c);
            float o0 = acc[i][j][0] + b2.x, o1 = acc[i][j][1] + b2.y;
            float o2 = acc[i][j][2] + b2.x, o3 = acc[i][j][3] + b2.y;
            if (Cf) {
                *(float2*)(Cf + (size_t)r0 * DMODEL + c) = make_float2(o0, o1);
                *(float2*)(Cf + (size_t)(r0 + 8) * DMODEL + c) = make_float2(o2, o3);
            } else {
                uint32_t hp, lp;
                split2(o0, o1, hp, lp);
                *(uint32_t*)(Chi + (size_t)r0 * DMODEL + c) = hp;
                *(uint32_t*)(Clo + (size_t)r0 * DMODEL + c) = lp;
                split2(o2, o3, hp, lp);
                *(uint32_t*)(Chi + (size_t)(r0 + 8) * DMODEL + c) = hp;
                *(uint32_t*)(Clo + (size_t)(r0 + 8) * DMODEL + c) = lp;
            }
        }
    }
}

// ---------------------------------------------------------------------------
// HMMA flash attention, bf16 hi/lo split, causal.
// Grid (32 q-tiles REVERSED, 16 heads), 256 threads (8 warps x 16 q-rows).
// KV double-buffered; one sync per tile; 2 CTAs/SM via launch bounds.
// ---------------------------------------------------------------------------
#define AROW     144
#define QT_B     (128 * AROW)          // 18432 per Q array
#define KV_B     (64 * AROW)           // 9216 per KV array
#define KV_BASE  (2 * QT_B)            // 36864
#define KVSTG_B  (4 * KV_B)            // 36864 per stage
#define ATTN_SMEM (KV_BASE + 2 * KVSTG_B)  // 110592

__global__ __launch_bounds__(256, 2) void attn_mma_kernel(
    const __nv_bfloat16* __restrict__ Qhi, const __nv_bfloat16* __restrict__ Qlo,
    const __nv_bfloat16* __restrict__ Khi, const __nv_bfloat16* __restrict__ Klo,
    const __nv_bfloat16* __restrict__ Vhi, const __nv_bfloat16* __restrict__ Vlo,
    __nv_bfloat16* __restrict__ Ohi, __nv_bfloat16* __restrict__ Olo)
{
    extern __shared__ char sm_raw[];
    uint32_t sb = (uint32_t)__cvta_generic_to_shared(sm_raw);

    int tid  = threadIdx.x;
    int lane = tid & 31, w = tid >> 5;
    int g = lane >> 2, q = lane & 3;
    int head = blockIdx.y;
    int qb = (int)(gridDim.x - 1 - blockIdx.x);   // heavy tiles first
    int q0 = qb * 128;
    int col0 = head * DK;

    // ---- Q tile (hi+lo): 128 rows x 64 cols ----
    {
        const __nv_bfloat16* srcs[2] = {Qhi, Qlo};
        #pragma unroll
        for (int arr = 0; arr < 2; arr++)
            for (int c = tid; c < 1024; c += 256) {
                int row = c >> 3, ch = c & 7;
                const void* gp = srcs[arr] + (size_t)(q0 + row) * DMODEL + col0 + ch * 8;
                uint32_t dp = sb + arr * QT_B + row * AROW + ch * 16;
                asm volatile("cp.async.cg.shared.global [%0], [%1], 16;\n"
                             :: "r"(dp), "l"(gp));
            }
        asm volatile("cp.async.commit_group;\n" ::: "memory");
    }

    const __nv_bfloat16* kvsrc[4] = {Khi, Klo, Vhi, Vlo};
    auto issue_kv = [&](int kt, int stage) {
        int k0 = kt * 64;
        uint32_t st = sb + KV_BASE + stage * KVSTG_B;
        #pragma unroll
        for (int arr = 0; arr < 4; arr++)
            for (int c = tid; c < 512; c += 256) {
                int row = c >> 3, ch = c & 7;
                const void* gp = kvsrc[arr] + (size_t)(k0 + row) * DMODEL + col0 + ch * 8;
                uint32_t dp = st + arr * KV_B + row * AROW + ch * 16;
                asm volatile("cp.async.cg.shared.global [%0], [%1], 16;\n"
                             :: "r"(dp), "l"(gp));
            }
        asm volatile("cp.async.commit_group;\n" ::: "memory");
    };

    issue_kv(0, 0);
    asm volatile("cp.async.wait_group 0;\n" ::: "memory");
    __syncthreads();

    float o[8][4] = {};
    float m0r = -1e30f, m1r = -1e30f, l0r = 0.0f, l1r = 0.0f;
    const int r0 = q0 + w * 16;
    const int nt = 2 * qb + 2;
    int grp = lane >> 3;

    for (int kt = 0; kt < nt; kt++) {
        int k0 = kt * 64;
        if (kt + 1 < nt) issue_kv(kt + 1, (kt + 1) & 1);

        if (k0 <= r0 + 15) {
            uint32_t st  = sb + KV_BASE + (kt & 1) * KVSTG_B;
            uint32_t sQh = sb;
            uint32_t sKh = st;
            uint32_t sVh = st + 2 * KV_B;

            // ---- S = Q @ K^T (3-pass split) ----
            float s[8][4] = {};
            #pragma unroll
            for (int t = 0; t < 4; t++) {
                uint32_t qh[4], ql[4];
                uint32_t qa = sQh + (uint32_t)((w * 16 + (lane & 15)) * AROW
                                               + (t * 16 + (lane >> 4) * 8) * 2);
                ldm_x4(qh, qa);
                ldm_x4(ql, qa + QT_B);
                #pragma unroll
                for (int jp = 0; jp < 4; jp++) {
                    uint32_t bd = sKh + (uint32_t)(((jp * 2 + (grp >> 1)) * 8 + (lane & 7)) * AROW
                                                   + (t * 16 + (grp & 1) * 8) * 2);
                    uint32_t bh[4], bl[4];
                    ldm_x4(bh, bd);
                    ldm_x4(bl, bd + KV_B);
                    mma16816(s[jp * 2],     qh, bh[0], bh[1]);
                    mma16816(s[jp * 2],     qh, bl[0], bl[1]);
                    mma16816(s[jp * 2],     ql, bh[0], bh[1]);
                    mma16816(s[jp * 2 + 1], qh, bh[2], bh[3]);
                    mma16816(s[jp * 2 + 1], qh, bl[2], bl[3]);
                    mma16816(s[jp * 2 + 1], ql, bh[2], bh[3]);
                }
            }

            // ---- scale + causal mask ----
            bool need_mask = (k0 + 63 > r0);
            #pragma unroll
            for (int nb = 0; nb < 8; nb++)
                #pragma unroll
                for (int ci = 0; ci < 4; ci++) {
                    float v = s[nb][ci] * 0.125f;
                    if (need_mask) {
                        int row = r0 + g + (ci >> 1) * 8;
                        int key = k0 + nb * 8 + 2 * q + (ci & 1);
                        if (key > row) v = -1e30f;
                    }
                    s[nb][ci] = v;
                }

            // ---- online softmax (rows g and g+8) ----
            float mx0 = -1e30f, mx1 = -1e30f;
            #pragma unroll
            for (int nb = 0; nb < 8; nb++) {
                mx0 = fmaxf(mx0, fmaxf(s[nb][0], s[nb][1]));
                mx1 = fmaxf(mx1, fmaxf(s[nb][2], s[nb][3]));
            }
            mx0 = fmaxf(mx0, __shfl_xor_sync(0xffffffffu, mx0, 1));
            mx0 = fmaxf(mx0, __shfl_xor_sync(0xffffffffu, mx0, 2));
            mx1 = fmaxf(mx1, __shfl_xor_sync(0xffffffffu, mx1, 1));
            mx1 = fmaxf(mx1, __shfl_xor_sync(0xffffffffu, mx1, 2));
            float mn0 = fmaxf(m0r, mx0), mn1 = fmaxf(m1r, mx1);
            float a0 = __expf(m0r - mn0), a1 = __expf(m1r - mn1);
            float ls0 = 0.0f, ls1 = 0.0f;
            #pragma unroll
            for (int nb = 0; nb < 8; nb++) {
                float p0 = __expf(s[nb][0] - mn0);
                float p1 = __expf(s[nb][1] - mn0);
                float p2 = __expf(s[nb][2] - mn1);
                float p3 = __expf(s[nb][3] - mn1);
                s[nb][0] = p0; s[nb][1] = p1; s[nb][2] = p2; s[nb][3] = p3;
                ls0 += p0 + p1; ls1 += p2 + p3;
            }
            ls0 += __shfl_xor_sync(0xffffffffu, ls0, 1);
            ls0 += __shfl_xor_sync(0xffffffffu, ls0, 2);
            ls1 += __shfl_xor_sync(0xffffffffu, ls1, 1);
            ls1 += __shfl_xor_sync(0xffffffffu, ls1, 2);
            l0r = l0r * a0 + ls0; l1r = l1r * a1 + ls1;
            m0r = mn0; m1r = mn1;
            #pragma unroll
            for (int nb = 0; nb < 8; nb++) {
                o[nb][0] *= a0; o[nb][1] *= a0;
                o[nb][2] *= a1; o[nb][3] *= a1;
            }

            // ---- O += P @ V (3-pass split; P frags from S accumulators) ----
            #pragma unroll
            for (int t = 0; t < 4; t++) {
                uint32_t ph[4], pl[4];
                split2(s[2 * t][0],     s[2 * t][1],     ph[0], pl[0]);
                split2(s[2 * t][2],     s[2 * t][3],     ph[1], pl[1]);
                split2(s[2 * t + 1][0], s[2 * t + 1][1], ph[2], pl[2]);
                split2(s[2 * t + 1][2], s[2 * t + 1][3], ph[3], pl[3]);
                #pragma unroll
                for (int jp = 0; jp < 4; jp++) {
                    uint32_t vd = sVh + (uint32_t)((16 * t + (grp & 1) * 8 + (lane & 7)) * AROW
                                                   + ((jp * 2 + (grp >> 1)) * 8) * 2);
                    uint32_t vh[4], vl[4];
                    ldm_x4_t(vh, vd);
                    ldm_x4_t(vl, vd + KV_B);
                    mma16816(o[jp * 2],     ph, vh[0], vh[1]);
                    mma16816(o[jp * 2],     ph, vl[0], vl[1]);
                    mma16816(o[jp * 2],     pl, vh[0], vh[1]);
                    mma16816(o[jp * 2 + 1], ph, vh[2], vh[3]);
                    mma16816(o[jp * 2 + 1], ph, vl[2], vl[3]);
                    mma16816(o[jp * 2 + 1], pl, vh[2], vh[3]);
                }
            }
        }

        if (kt + 1 < nt) {
            asm volatile("cp.async.wait_group 0;\n" ::: "memory");
            __syncthreads();
        }
    }

    // ---- epilogue: normalize, hi/lo split, store ----
    float inv0 = 1.0f / l0r, inv1 = 1.0f / l1r;
    int row0 = q0 + w * 16 + g;
    int row1 = row0 + 8;
    #pragma unroll
    for (int nb = 0; nb < 8; nb++) {
        int c = col0 + nb * 8 + 2 * q;
        uint32_t hp, lp;
        split2(o[nb][0] * inv0, o[nb][1] * inv0, hp, lp);
        *(uint32_t*)(Ohi + (size_t)row0 * DMODEL + c) = hp;
        *(uint32_t*)(Olo + (size_t)row0 * DMODEL + c) = lp;
        split2(o[nb][2] * inv1, o[nb][3] * inv1, hp, lp);
        *(uint32_t*)(Ohi + (size_t)row1 * DMODEL + c) = hp;
        *(uint32_t*)(Olo + (size_t)row1 * DMODEL + c) = lp;
    }
}

// ---------------------------------------------------------------------------
extern "C" void kernel_launch(void* const* d_in, const int* in_sizes, int n_in,
                              void* d_out, int out_size)
{
    const float* x  = (const float*)d_in[0];
    const float* Wq = (const float*)d_in[1];
    const float* bq = (const float*)d_in[2];
    const float* Wk = (const float*)d_in[3];
    const float* bk = (const float*)d_in[4];
    const float* Wv = (const float*)d_in[5];
    const float* bv = (const float*)d_in[6];
    const float* Wo = (const float*)d_in[7];
    const float* bo = (const float*)d_in[8];
    float* out = (float*)d_out;

    __nv_bfloat16 *xhi, *xlo, *qhi, *qlo, *khi, *klo, *vhi, *vlo;
    __nv_bfloat16 *wqh, *wql, *wkh, *wkl, *wvh, *wvl, *woh, *wol;
    cudaGetSymbolAddress((void**)&xhi, g_xhi);
    cudaGetSymbolAddress((void**)&xlo, g_xlo);
    cudaGetSymbolAddress((void**)&qhi, g_qhi);
    cudaGetSymbolAddress((void**)&qlo, g_qlo);
    cudaGetSymbolAddress((void**)&khi, g_khi);
    cudaGetSymbolAddress((void**)&klo, g_klo);
    cudaGetSymbolAddress((void**)&vhi, g_vhi);
    cudaGetSymbolAddress((void**)&vlo, g_vlo);
    cudaGetSymbolAddress((void**)&wqh, g_wqhi);
    cudaGetSymbolAddress((void**)&wql, g_wqlo);
    cudaGetSymbolAddress((void**)&wkh, g_wkhi);
    cudaGetSymbolAddress((void**)&wkl, g_wklo);
    cudaGetSymbolAddress((void**)&wvh, g_wvhi);
    cudaGetSymbolAddress((void**)&wvl, g_wvlo);
    cudaGetSymbolAddress((void**)&woh, g_wohi);
    cudaGetSymbolAddress((void**)&wol, g_wolo);

    cudaFuncSetAttribute(gemm_mma_kernel,
                         cudaFuncAttributeMaxDynamicSharedMemorySize, GEMM_SMEM);
    cudaFuncSetAttribute(attn_mma_kernel,
                         cudaFuncAttributeMaxDynamicSharedMemorySize, ATTN_SMEM);

    const int NX4 = S_LEN * DMODEL / 4;
    const int NW4 = DMODEL * DMODEL / 4;

    cvt_split_kernel<<<(NX4 + 255) / 256, 256>>>(x, xhi, xlo, NX4);
    cvt_split4_kernel<<<dim3((NW4 + 255) / 256, 4), 256>>>(
        Wq, Wk, Wv, Wo, wqh, wkh, wvh, woh, wql, wkl, wvl, wol, NW4);

    dim3 ggrid(DMODEL / 128, S_LEN / 128);
    gemm_mma_kernel<<<ggrid, 256, GEMM_SMEM>>>(xhi, xlo, wqh, wql, bq,
                                               nullptr, qhi, qlo, DMODEL);
    gemm_mma_kernel<<<ggrid, 256, GEMM_SMEM>>>(xhi, xlo, wkh, wkl, bk,
                                               nullptr, khi, klo, DMODEL);
    gemm_mma_kernel<<<ggrid, 256, GEMM_SMEM>>>(xhi, xlo, wvh, wvl, bv,
                                               nullptr, vhi, vlo, DMODEL);

    // attention writes its bf16 hi/lo output into xhi/xlo (x splits consumed)
    attn_mma_kernel<<<dim3(S_LEN / 128, NHEADS), 256, ATTN_SMEM>>>(
        qhi, qlo, khi, klo, vhi, vlo, xhi, xlo);

    gemm_mma_kernel<<<ggrid, 256, GEMM_SMEM>>>(xhi, xlo, woh, wol, bo,
                                               out, nullptr, nullptr, DMODEL);
}

// round 15
// speedup vs baseline: 1.0875x; 1.0875x over previous
#include <cuda_runtime.h>
#include <cuda_bf16.h>
#include <cstdint>
#include <math.h>

#define S_LEN   4096
#define DMODEL  1024
#define NHEADS  16
#define DK      64

// ---------------- scratch (__device__ globals: allocation-free) ------------
__device__ __nv_bfloat16 g_xhi[S_LEN * DMODEL];   // x hi; later reused: attn-out hi
__device__ __nv_bfloat16 g_xlo[S_LEN * DMODEL];   // x lo; later reused: attn-out lo
__device__ __nv_bfloat16 g_qhi[S_LEN * DMODEL];
__device__ __nv_bfloat16 g_qlo[S_LEN * DMODEL];
__device__ __nv_bfloat16 g_khi[S_LEN * DMODEL];
__device__ __nv_bfloat16 g_klo[S_LEN * DMODEL];
__device__ __nv_bfloat16 g_vhi[S_LEN * DMODEL];
__device__ __nv_bfloat16 g_vlo[S_LEN * DMODEL];
__device__ __nv_bfloat16 g_wqhi[DMODEL * DMODEL];
__device__ __nv_bfloat16 g_wqlo[DMODEL * DMODEL];
__device__ __nv_bfloat16 g_wkhi[DMODEL * DMODEL];
__device__ __nv_bfloat16 g_wklo[DMODEL * DMODEL];
__device__ __nv_bfloat16 g_wvhi[DMODEL * DMODEL];
__device__ __nv_bfloat16 g_wvlo[DMODEL * DMODEL];
__device__ __nv_bfloat16 g_wohi[DMODEL * DMODEL];
__device__ __nv_bfloat16 g_wolo[DMODEL * DMODEL];

// ---------------------------------------------------------------------------
// helpers
// ---------------------------------------------------------------------------
__device__ __forceinline__ void split_store(const float4 v,
    __nv_bfloat16* hi, __nv_bfloat16* lo, int i)
{
    __nv_bfloat16 h0 = __float2bfloat16(v.x);
    __nv_bfloat16 h1 = __float2bfloat16(v.y);
    __nv_bfloat16 h2 = __float2bfloat16(v.z);
    __nv_bfloat16 h3 = __float2bfloat16(v.w);
    __nv_bfloat16 l0 = __float2bfloat16(v.x - __bfloat162float(h0));
    __nv_bfloat16 l1 = __float2bfloat16(v.y - __bfloat162float(h1));
    __nv_bfloat16 l2 = __float2bfloat16(v.z - __bfloat162float(h2));
    __nv_bfloat16 l3 = __float2bfloat16(v.w - __bfloat162float(h3));
    ((__nv_bfloat162*)hi)[2 * i + 0] = __nv_bfloat162(h0, h1);
    ((__nv_bfloat162*)hi)[2 * i + 1] = __nv_bfloat162(h2, h3);
    ((__nv_bfloat162*)lo)[2 * i + 0] = __nv_bfloat162(l0, l1);
    ((__nv_bfloat162*)lo)[2 * i + 1] = __nv_bfloat162(l2, l3);
}

// batched: matrix 0 (x) has n4x float4s; matrices 1-4 (weights) have n4w each
__global__ __launch_bounds__(256) void cvt_split5_kernel(
    const float* s0, const float* s1, const float* s2, const float* s3,
    const float* s4,
    __nv_bfloat16* h0, __nv_bfloat16* h1, __nv_bfloat16* h2, __nv_bfloat16* h3,
    __nv_bfloat16* h4,
    __nv_bfloat16* l0, __nv_bfloat16* l1, __nv_bfloat16* l2, __nv_bfloat16* l3,
    __nv_bfloat16* l4, int n4x, int n4w)
{
    int i = blockIdx.x * 256 + threadIdx.x;
    const float* src;
    __nv_bfloat16 *hi, *lo;
    int n4;
    switch (blockIdx.y) {
        case 0: src = s0; hi = h0; lo = l0; n4 = n4x; break;
        case 1: src = s1; hi = h1; lo = l1; n4 = n4w; break;
        case 2: src = s2; hi = h2; lo = l2; n4 = n4w; break;
        case 3: src = s3; hi = h3; lo = l3; n4 = n4w; break;
        default: src = s4; hi = h4; lo = l4; n4 = n4w; break;
    }
    if (i >= n4) return;
    split_store(((const float4*)src)[i], hi, lo, i);
}

__device__ __forceinline__ void mma16816(float* c, const uint32_t* a,
                                         uint32_t b0, uint32_t b1) {
    asm volatile(
        "mma.sync.aligned.m16n8k16.row.col.f32.bf16.bf16.f32 "
        "{%0,%1,%2,%3}, {%4,%5,%6,%7}, {%8,%9}, {%0,%1,%2,%3};\n"
        : "+f"(c[0]), "+f"(c[1]), "+f"(c[2]), "+f"(c[3])
        : "r"(a[0]), "r"(a[1]), "r"(a[2]), "r"(a[3]), "r"(b0), "r"(b1));
}

__device__ __forceinline__ void ldm_x4(uint32_t* r, uint32_t addr) {
    asm volatile("ldmatrix.sync.aligned.m8n8.x4.shared.b16 {%0,%1,%2,%3}, [%4];"
        : "=r"(r[0]), "=r"(r[1]), "=r"(r[2]), "=r"(r[3]) : "r"(addr));
}

__device__ __forceinline__ void ldm_x4_t(uint32_t* r, uint32_t addr) {
    asm volatile("ldmatrix.sync.aligned.m8n8.x4.trans.shared.b16 {%0,%1,%2,%3}, [%4];"
        : "=r"(r[0]), "=r"(r[1]), "=r"(r[2]), "=r"(r[3]) : "r"(addr));
}

__device__ __forceinline__ void split2(float x, float y, uint32_t& hi, uint32_t& lo) {
    __nv_bfloat16 hx = __float2bfloat16(x), hy = __float2bfloat16(y);
    __nv_bfloat16 lx = __float2bfloat16(x - __bfloat162float(hx));
    __nv_bfloat16 ly = __float2bfloat16(y - __bfloat162float(hy));
    __nv_bfloat162 h(hx, hy), l(lx, ly);
    hi = *(uint32_t*)&h; lo = *(uint32_t*)&l;
}

// ---------------------------------------------------------------------------
// bf16-split HMMA GEMM: C = (Ahi+Alo)[M,K] @ (Bhi+Blo)[N,K]^T + bias
// CTA 128x128, BK=32, 8 warps. 3-stage cp.async ring with wait_group 1;
// swizzled 64B rows (no padding). 2 CTAs/SM. blockIdx.z selects weight set.
// ---------------------------------------------------------------------------
#define GBK      32
#define TILE_B   8192              // 128 rows * 64B (swizzled, no pad)
#define STAGE_B  (4 * TILE_B)      // 32768
#define NSTAGE   3
#define GEMM_SMEM (NSTAGE * STAGE_B)  // 98304

struct GemmBatch {
    const __nv_bfloat16* bh[3];
    const __nv_bfloat16* bl[3];
    const float* bias[3];
    __nv_bfloat16* ch[3];
    __nv_bfloat16* cl[3];
    float* cf[3];
};

__global__ __launch_bounds__(256, 2) void gemm_mma_kernel(
    const __nv_bfloat16* __restrict__ Ahi, const __nv_bfloat16* __restrict__ Alo,
    GemmBatch gb, int K)
{
    extern __shared__ char sm_raw[];
    int tid  = threadIdx.x;
    int lane = tid & 31, wid = tid >> 5;
    int g = lane >> 2;
    int q = lane & 3;
    int warpM = (wid & 3) * 32;
    int warpN = (wid >> 2) * 64;
    int n0 = blockIdx.x * 128;
    int m0 = blockIdx.y * 128;
    int z  = blockIdx.z;

    const __nv_bfloat16* Bhi = gb.bh[z];
    const __nv_bfloat16* Blo = gb.bl[z];
    const float* bias = gb.bias[z];
    __nv_bfloat16* Chi = gb.ch[z];
    __nv_bfloat16* Clo = gb.cl[z];
    float* Cf = gb.cf[z];

    uint32_t sbase = (uint32_t)__cvta_generic_to_shared(sm_raw);

    float acc[2][8][4] = {};
    const __nv_bfloat16* srcs[4] = {Ahi, Alo, Bhi, Blo};

    // 4 tiles of [128][32] bf16, 64B rows, swizzle: chunk ^= (row>>1)&3
    auto issue_loads = [&](int stage, int k0) {
        uint32_t st = sbase + stage * STAGE_B;
        int row4 = tid >> 2;      // 0..63
        int ch   = tid & 3;
        #pragma unroll
        for (int t = 0; t < 4; t++) {
            int rbase = (t < 2) ? m0 : n0;
            #pragma unroll
            for (int h = 0; h < 2; h++) {
                int row = row4 + h * 64;
                const void* gp = srcs[t] + (size_t)(rbase + row) * K + k0 + ch * 8;
                int sw = ch ^ ((row >> 1) & 3);
                uint32_t dp = st + t * TILE_B + row * 64 + sw * 16;
                asm volatile("cp.async.cg.shared.global [%0], [%1], 16;\n"
                             :: "r"(dp), "l"(gp));
            }
        }
        asm volatile("cp.async.commit_group;\n" ::: "memory");
    };

    auto compute = [&](int stage) {
        uint32_t st = sbase + stage * STAGE_B;
        uint32_t sA = st;               // Ahi; Alo at +TILE_B
        uint32_t sB = st + 2 * TILE_B;  // Bhi; Blo at +TILE_B
        int grp = lane >> 3;
        #pragma unroll
        for (int ks = 0; ks < GBK; ks += 16) {
            uint32_t ah[2][4], al[2][4];
            #pragma unroll
            for (int i = 0; i < 2; i++) {
                int ar = warpM + i * 16 + (lane & 15);
                int kc = (ks >> 3) + (lane >> 4);
                uint32_t ad = sA + (uint32_t)(ar * 64 + (kc ^ ((ar >> 1) & 3)) * 16);
                ldm_x4(ah[i], ad);
                ldm_x4(al[i], ad + TILE_B);
            }
            #pragma unroll
            for (int jp = 0; jp < 4; jp++) {
                int br = warpN + (jp * 2 + (grp >> 1)) * 8 + (lane & 7);
                int kc = (ks >> 3) + (grp & 1);
                uint32_t bd = sB + (uint32_t)(br * 64 + (kc ^ ((br >> 1) & 3)) * 16);
                uint32_t bh[4], bl[4];
                ldm_x4(bh, bd);
                ldm_x4(bl, bd + TILE_B);
                #pragma unroll
                for (int i = 0; i < 2; i++) {
                    mma16816(acc[i][jp * 2],     ah[i], bh[0], bh[1]);
                    mma16816(acc[i][jp * 2],     ah[i], bl[0], bl[1]);
                    mma16816(acc[i][jp * 2],     al[i], bh[0], bh[1]);
                    mma16816(acc[i][jp * 2 + 1], ah[i], bh[2], bh[3]);
                    mma16816(acc[i][jp * 2 + 1], ah[i], bl[2], bl[3]);
                    mma16816(acc[i][jp * 2 + 1], al[i], bh[2], bh[3]);
                }
            }
        }
    };

    const int NITER = K / GBK;    // 32
    issue_loads(0, 0);
    issue_loads(1, GBK);
    asm volatile("cp.async.wait_group 1;\n" ::: "memory");
    __syncthreads();
    for (int it = 0; it < NITER; it++) {
        if (it + 2 < NITER) {
            int nx = it + 2;
            int stg = nx - (nx / NSTAGE) * NSTAGE;
            issue_loads(stg, nx * GBK);
        }
        compute(it - (it / NSTAGE) * NSTAGE);
        if (it + 1 < NITER) {
            if (it + 2 < NITER) {
                asm volatile("cp.async.wait_group 1;\n" ::: "memory");
            } else {
                asm volatile("cp.async.wait_group 0;\n" ::: "memory");
            }
            __syncthreads();
        }
    }

    // --- epilogue ---
    #pragma unroll
    for (int i = 0; i < 2; i++) {
        int r0 = m0 + warpM + i * 16 + g;
        #pragma unroll
        for (int j = 0; j < 8; j++) {
            int c = n0 + warpN + j * 8 + q * 2;
            float2 b2 = *(const float2*)(bias + c);
            float o0 = acc[i][j][0] + b2.x, o1 = acc[i][j][1] + b2.y;
            float o2 = acc[i][j][2] + b2.x, o3 = acc[i][j][3] + b2.y;
            if (Cf) {
                *(float2*)(Cf + (size_t)r0 * DMODEL + c) = make_float2(o0, o1);
                *(float2*)(Cf + (size_t)(r0 + 8) * DMODEL + c) = make_float2(o2, o3);
            } else {
                uint32_t hp, lp;
                split2(o0, o1, hp, lp);
                *(uint32_t*)(Chi + (size_t)r0 * DMODEL + c) = hp;
                *(uint32_t*)(Clo + (size_t)r0 * DMODEL + c) = lp;
                split2(o2, o3, hp, lp);
                *(uint32_t*)(Chi + (size_t)(r0 + 8) * DMODEL + c) = hp;
                *(uint32_t*)(Clo + (size_t)(r0 + 8) * DMODEL + c) = lp;
            }
        }
    }
}

// ---------------------------------------------------------------------------
// HMMA flash attention, bf16 hi/lo split, causal.  (unchanged, known good)
// ---------------------------------------------------------------------------
#define AROW     144
#define QT_B     (128 * AROW)
#define KV_B     (64 * AROW)
#define KV_BASE  (2 * QT_B)
#define KVSTG_B  (4 * KV_B)
#define ATTN_SMEM (KV_BASE + 2 * KVSTG_B)  // 110592

__global__ __launch_bounds__(256, 2) void attn_mma_kernel(
    const __nv_bfloat16* __restrict__ Qhi, const __nv_bfloat16* __restrict__ Qlo,
    const __nv_bfloat16* __restrict__ Khi, const __nv_bfloat16* __restrict__ Klo,
    const __nv_bfloat16* __restrict__ Vhi, const __nv_bfloat16* __restrict__ Vlo,
    __nv_bfloat16* __restrict__ Ohi, __nv_bfloat16* __restrict__ Olo)
{
    extern __shared__ char sm_raw[];
    uint32_t sb = (uint32_t)__cvta_generic_to_shared(sm_raw);

    int tid  = threadIdx.x;
    int lane = tid & 31, w = tid >> 5;
    int g = lane >> 2, q = lane & 3;
    int head = blockIdx.y;
    int qb = (int)(gridDim.x - 1 - blockIdx.x);   // heavy tiles first
    int q0 = qb * 128;
    int col0 = head * DK;

    {
        const __nv_bfloat16* srcs[2] = {Qhi, Qlo};
        #pragma unroll
        for (int arr = 0; arr < 2; arr++)
            for (int c = tid; c < 1024; c += 256) {
                int row = c >> 3, ch = c & 7;
                const void* gp = srcs[arr] + (size_t)(q0 + row) * DMODEL + col0 + ch * 8;
                uint32_t dp = sb + arr * QT_B + row * AROW + ch * 16;
                asm volatile("cp.async.cg.shared.global [%0], [%1], 16;\n"
                             :: "r"(dp), "l"(gp));
            }
        asm volatile("cp.async.commit_group;\n" ::: "memory");
    }

    const __nv_bfloat16* kvsrc[4] = {Khi, Klo, Vhi, Vlo};
    auto issue_kv = [&](int kt, int stage) {
        int k0 = kt * 64;
        uint32_t st = sb + KV_BASE + stage * KVSTG_B;
        #pragma unroll
        for (int arr = 0; arr < 4; arr++)
            for (int c = tid; c < 512; c += 256) {
                int row = c >> 3, ch = c & 7;
                const void* gp = kvsrc[arr] + (size_t)(k0 + row) * DMODEL + col0 + ch * 8;
                uint32_t dp = st + arr * KV_B + row * AROW + ch * 16;
                asm volatile("cp.async.cg.shared.global [%0], [%1], 16;\n"
                             :: "r"(dp), "l"(gp));
            }
        asm volatile("cp.async.commit_group;\n" ::: "memory");
    };

    issue_kv(0, 0);
    asm volatile("cp.async.wait_group 0;\n" ::: "memory");
    __syncthreads();

    float o[8][4] = {};
    float m0r = -1e30f, m1r = -1e30f, l0r = 0.0f, l1r = 0.0f;
    const int r0 = q0 + w * 16;
    const int nt = 2 * qb + 2;
    int grp = lane >> 3;

    for (int kt = 0; kt < nt; kt++) {
        int k0 = kt * 64;
        if (kt + 1 < nt) issue_kv(kt + 1, (kt + 1) & 1);

        if (k0 <= r0 + 15) {
            uint32_t st  = sb + KV_BASE + (kt & 1) * KVSTG_B;
            uint32_t sQh = sb;
            uint32_t sKh = st;
            uint32_t sVh = st + 2 * KV_B;

            float s[8][4] = {};
            #pragma unroll
            for (int t = 0; t < 4; t++) {
                uint32_t qh[4], ql[4];
                uint32_t qa = sQh + (uint32_t)((w * 16 + (lane & 15)) * AROW
                                               + (t * 16 + (lane >> 4) * 8) * 2);
                ldm_x4(qh, qa);
                ldm_x4(ql, qa + QT_B);
                #pragma unroll
                for (int jp = 0; jp < 4; jp++) {
                    uint32_t bd = sKh + (uint32_t)(((jp * 2 + (grp >> 1)) * 8 + (lane & 7)) * AROW
                                                   + (t * 16 + (grp & 1) * 8) * 2);
                    uint32_t bh[4], bl[4];
                    ldm_x4(bh, bd);
                    ldm_x4(bl, bd + KV_B);
                    mma16816(s[jp * 2],     qh, bh[0], bh[1]);
                    mma16816(s[jp * 2],     qh, bl[0], bl[1]);
                    mma16816(s[jp * 2],     ql, bh[0], bh[1]);
                    mma16816(s[jp * 2 + 1], qh, bh[2], bh[3]);
                    mma16816(s[jp * 2 + 1], qh, bl[2], bl[3]);
                    mma16816(s[jp * 2 + 1], ql, bh[2], bh[3]);
                }
            }

            bool need_mask = (k0 + 63 > r0);
            #pragma unroll
            for (int nb = 0; nb < 8; nb++)
                #pragma unroll
                for (int ci = 0; ci < 4; ci++) {
                    float v = s[nb][ci] * 0.125f;
                    if (need_mask) {
                        int row = r0 + g + (ci >> 1) * 8;
                        int key = k0 + nb * 8 + 2 * q + (ci & 1);
                        if (key > row) v = -1e30f;
                    }
                    s[nb][ci] = v;
                }

            float mx0 = -1e30f, mx1 = -1e30f;
            #pragma unroll
            for (int nb = 0; nb < 8; nb++) {
                mx0 = fmaxf(mx0, fmaxf(s[nb][0], s[nb][1]));
                mx1 = fmaxf(mx1, fmaxf(s[nb][2], s[nb][3]));
            }
            mx0 = fmaxf(mx0, __shfl_xor_sync(0xffffffffu, mx0, 1));
            mx0 = fmaxf(mx0, __shfl_xor_sync(0xffffffffu, mx0, 2));
            mx1 = fmaxf(mx1, __shfl_xor_sync(0xffffffffu, mx1, 1));
            mx1 = fmaxf(mx1, __shfl_xor_sync(0xffffffffu, mx1, 2));
            float mn0 = fmaxf(m0r, mx0), mn1 = fmaxf(m1r, mx1);
            float a0 = __expf(m0r - mn0), a1 = __expf(m1r - mn1);
            float ls0 = 0.0f, ls1 = 0.0f;
            #pragma unroll
            for (int nb = 0; nb < 8; nb++) {
                float p0 = __expf(s[nb][0] - mn0);
                float p1 = __expf(s[nb][1] - mn0);
                float p2 = __expf(s[nb][2] - mn1);
                float p3 = __expf(s[nb][3] - mn1);
                s[nb][0] = p0; s[nb][1] = p1; s[nb][2] = p2; s[nb][3] = p3;
                ls0 += p0 + p1; ls1 += p2 + p3;
            }
            ls0 += __shfl_xor_sync(0xffffffffu, ls0, 1);
            ls0 += __shfl_xor_sync(0xffffffffu, ls0, 2);
            ls1 += __shfl_xor_sync(0xffffffffu, ls1, 1);
            ls1 += __shfl_xor_sync(0xffffffffu, ls1, 2);
            l0r = l0r * a0 + ls0; l1r = l1r * a1 + ls1;
            m0r = mn0; m1r = mn1;
            #pragma unroll
            for (int nb = 0; nb < 8; nb++) {
                o[nb][0] *= a0; o[nb][1] *= a0;
                o[nb][2] *= a1; o[nb][3] *= a1;
            }

            #pragma unroll
            for (int t = 0; t < 4; t++) {
                uint32_t ph[4], pl[4];
                split2(s[2 * t][0],     s[2 * t][1],     ph[0], pl[0]);
                split2(s[2 * t][2],     s[2 * t][3],     ph[1], pl[1]);
                split2(s[2 * t + 1][0], s[2 * t + 1][1], ph[2], pl[2]);
                split2(s[2 * t + 1][2], s[2 * t + 1][3], ph[3], pl[3]);
                #pragma unroll
                for (int jp = 0; jp < 4; jp++) {
                    uint32_t vd = sVh + (uint32_t)((16 * t + (grp & 1) * 8 + (lane & 7)) * AROW
                                                   + ((jp * 2 + (grp >> 1)) * 8) * 2);
                    uint32_t vh[4], vl[4];
                    ldm_x4_t(vh, vd);
                    ldm_x4_t(vl, vd + KV_B);
                    mma16816(o[jp * 2],     ph, vh[0], vh[1]);
                    mma16816(o[jp * 2],     ph, vl[0], vl[1]);
                    mma16816(o[jp * 2],     pl, vh[0], vh[1]);
                    mma16816(o[jp * 2 + 1], ph, vh[2], vh[3]);
                    mma16816(o[jp * 2 + 1], ph, vl[2], vl[3]);
                    mma16816(o[jp * 2 + 1], pl, vh[2], vh[3]);
                }
            }
        }

        if (kt + 1 < nt) {
            asm volatile("cp.async.wait_group 0;\n" ::: "memory");
            __syncthreads();
        }
    }

    float inv0 = 1.0f / l0r, inv1 = 1.0f / l1r;
    int row0 = q0 + w * 16 + g;
    int row1 = row0 + 8;
    #pragma unroll
    for (int nb = 0; nb < 8; nb++) {
        int c = col0 + nb * 8 + 2 * q;
        uint32_t hp, lp;
        split2(o[nb][0] * inv0, o[nb][1] * inv0, hp, lp);
        *(uint32_t*)(Ohi + (size_t)row0 * DMODEL + c) = hp;
        *(uint32_t*)(Olo + (size_t)row0 * DMODEL + c) = lp;
        split2(o[nb][2] * inv1, o[nb][3] * inv1, hp, lp);
        *(uint32_t*)(Ohi + (size_t)row1 * DMODEL + c) = hp;
        *(uint32_t*)(Olo + (size_t)row1 * DMODEL + c) = lp;
    }
}

// ---------------------------------------------------------------------------
extern "C" void kernel_launch(void* const* d_in, const int* in_sizes, int n_in,
                              void* d_out, int out_size)
{
    const float* x  = (const float*)d_in[0];
    const float* Wq = (const float*)d_in[1];
    const float* bq = (const float*)d_in[2];
    const float* Wk = (const float*)d_in[3];
    const float* bk = (const float*)d_in[4];
    const float* Wv = (const float*)d_in[5];
    const float* bv = (const float*)d_in[6];
    const float* Wo = (const float*)d_in[7];
    const float* bo = (const float*)d_in[8];
    float* out = (float*)d_out;

    __nv_bfloat16 *xhi, *xlo, *qhi, *qlo, *khi, *klo, *vhi, *vlo;
    __nv_bfloat16 *wqh, *wql, *wkh, *wkl, *wvh, *wvl, *woh, *wol;
    cudaGetSymbolAddress((void**)&xhi, g_xhi);
    cudaGetSymbolAddress((void**)&xlo, g_xlo);
    cudaGetSymbolAddress((void**)&qhi, g_qhi);
    cudaGetSymbolAddress((void**)&qlo, g_qlo);
    cudaGetSymbolAddress((void**)&khi, g_khi);
    cudaGetSymbolAddress((void**)&klo, g_klo);
    cudaGetSymbolAddress((void**)&vhi, g_vhi);
    cudaGetSymbolAddress((void**)&vlo, g_vlo);
    cudaGetSymbolAddress((void**)&wqh, g_wqhi);
    cudaGetSymbolAddress((void**)&wql, g_wqlo);
    cudaGetSymbolAddress((void**)&wkh, g_wkhi);
    cudaGetSymbolAddress((void**)&wkl, g_wklo);
    cudaGetSymbolAddress((void**)&wvh, g_wvhi);
    cudaGetSymbolAddress((void**)&wvl, g_wvlo);
    cudaGetSymbolAddress((void**)&woh, g_wohi);
    cudaGetSymbolAddress((void**)&wol, g_wolo);

    cudaFuncSetAttribute(gemm_mma_kernel,
                         cudaFuncAttributeMaxDynamicSharedMemorySize, GEMM_SMEM);
    cudaFuncSetAttribute(attn_mma_kernel,
                         cudaFuncAttributeMaxDynamicSharedMemorySize, ATTN_SMEM);

    const int NX4 = S_LEN * DMODEL / 4;    // 1,048,576 float4 (x)
    const int NW4 = DMODEL * DMODEL / 4;   //   262,144 float4 (each weight)

    cvt_split5_kernel<<<dim3((NX4 + 255) / 256, 5), 256>>>(
        x, Wq, Wk, Wv, Wo,
        xhi, wqh, wkh, wvh, woh,
        xlo, wql, wkl, wvl, wol, NX4, NW4);

    // fused Q/K/V projections: gridDim.z = 3 selects weight/output set
    GemmBatch qkv;
    qkv.bh[0] = wqh; qkv.bl[0] = wql; qkv.bias[0] = bq;
    qkv.ch[0] = qhi; qkv.cl[0] = qlo; qkv.cf[0] = nullptr;
    qkv.bh[1] = wkh; qkv.bl[1] = wkl; qkv.bias[1] = bk;
    qkv.ch[1] = khi; qkv.cl[1] = klo; qkv.cf[1] = nullptr;
    qkv.bh[2] = wvh; qkv.bl[2] = wvl; qkv.bias[2] = bv;
    qkv.ch[2] = vhi; qkv.cl[2] = vlo; qkv.cf[2] = nullptr;
    gemm_mma_kernel<<<dim3(DMODEL / 128, S_LEN / 128, 3), 256, GEMM_SMEM>>>(
        xhi, xlo, qkv, DMODEL);

    // attention writes its bf16 hi/lo output into xhi/xlo (x splits consumed)
    attn_mma_kernel<<<dim3(S_LEN / 128, NHEADS), 256, ATTN_SMEM>>>(
        qhi, qlo, khi, klo, vhi, vlo, xhi, xlo);

    // output projection (fp32 out)
    GemmBatch ob;
    ob.bh[0] = woh; ob.bl[0] = wol; ob.bias[0] = bo;
    ob.ch[0] = nullptr; ob.cl[0] = nullptr; ob.cf[0] = out;
    ob.bh[1] = ob.bh[0]; ob.bl[1] = ob.bl[0]; ob.bias[1] = ob.bias[0];
    ob.ch[1] = nullptr; ob.cl[1] = nullptr; ob.cf[1] = out;
    ob.bh[2] = ob.bh[0]; ob.bl[2] = ob.bl[0]; ob.bias[2] = ob.bias[0];
    ob.ch[2] = nullptr; ob.cl[2] = nullptr; ob.cf[2] = out;
    gemm_mma_kernel<<<dim3(DMODEL / 128, S_LEN / 128, 1), 256, GEMM_SMEM>>>(
        xhi, xlo, ob, DMODEL);
}

// round 17
// speedup vs baseline: 1.0893x; 1.0017x over previous
#include <cuda_runtime.h>
#include <cuda_bf16.h>
#include <cstdint>
#include <math.h>

#define S_LEN   4096
#define DMODEL  1024
#define NHEADS  16
#define DK      64

// ---------------- scratch (__device__ globals: allocation-free) ------------
__device__ __nv_bfloat16 g_xhi[S_LEN * DMODEL];   // x hi; later reused: attn-out hi
__device__ __nv_bfloat16 g_xlo[S_LEN * DMODEL];   // x lo; later reused: attn-out lo
__device__ __nv_bfloat16 g_qhi[S_LEN * DMODEL];
__device__ __nv_bfloat16 g_qlo[S_LEN * DMODEL];
__device__ __nv_bfloat16 g_khi[S_LEN * DMODEL];
__device__ __nv_bfloat16 g_klo[S_LEN * DMODEL];
__device__ __nv_bfloat16 g_vhi[S_LEN * DMODEL];
__device__ __nv_bfloat16 g_vlo[S_LEN * DMODEL];
__device__ __nv_bfloat16 g_wqhi[DMODEL * DMODEL];
__device__ __nv_bfloat16 g_wqlo[DMODEL * DMODEL];
__device__ __nv_bfloat16 g_wkhi[DMODEL * DMODEL];
__device__ __nv_bfloat16 g_wklo[DMODEL * DMODEL];
__device__ __nv_bfloat16 g_wvhi[DMODEL * DMODEL];
__device__ __nv_bfloat16 g_wvlo[DMODEL * DMODEL];
__device__ __nv_bfloat16 g_wohi[DMODEL * DMODEL];
__device__ __nv_bfloat16 g_wolo[DMODEL * DMODEL];

// ---------------------------------------------------------------------------
// helpers
// ---------------------------------------------------------------------------
__device__ __forceinline__ void split_store(const float4 v,
    __nv_bfloat16* hi, __nv_bfloat16* lo, int i)
{
    __nv_bfloat16 h0 = __float2bfloat16(v.x);
    __nv_bfloat16 h1 = __float2bfloat16(v.y);
    __nv_bfloat16 h2 = __float2bfloat16(v.z);
    __nv_bfloat16 h3 = __float2bfloat16(v.w);
    __nv_bfloat16 l0 = __float2bfloat16(v.x - __bfloat162float(h0));
    __nv_bfloat16 l1 = __float2bfloat16(v.y - __bfloat162float(h1));
    __nv_bfloat16 l2 = __float2bfloat16(v.z - __bfloat162float(h2));
    __nv_bfloat16 l3 = __float2bfloat16(v.w - __bfloat162float(h3));
    ((__nv_bfloat162*)hi)[2 * i + 0] = __nv_bfloat162(h0, h1);
    ((__nv_bfloat162*)hi)[2 * i + 1] = __nv_bfloat162(h2, h3);
    ((__nv_bfloat162*)lo)[2 * i + 0] = __nv_bfloat162(l0, l1);
    ((__nv_bfloat162*)lo)[2 * i + 1] = __nv_bfloat162(l2, l3);
}

// batched: matrix 0 (x) has n4x float4s; matrices 1-4 (weights) have n4w each
__global__ __launch_bounds__(256) void cvt_split5_kernel(
    const float* s0, const float* s1, const float* s2, const float* s3,
    const float* s4,
    __nv_bfloat16* h0, __nv_bfloat16* h1, __nv_bfloat16* h2, __nv_bfloat16* h3,
    __nv_bfloat16* h4,
    __nv_bfloat16* l0, __nv_bfloat16* l1, __nv_bfloat16* l2, __nv_bfloat16* l3,
    __nv_bfloat16* l4, int n4x, int n4w)
{
    int i = blockIdx.x * 256 + threadIdx.x;
    const float* src;
    __nv_bfloat16 *hi, *lo;
    int n4;
    switch (blockIdx.y) {
        case 0: src = s0; hi = h0; lo = l0; n4 = n4x; break;
        case 1: src = s1; hi = h1; lo = l1; n4 = n4w; break;
        case 2: src = s2; hi = h2; lo = l2; n4 = n4w; break;
        case 3: src = s3; hi = h3; lo = l3; n4 = n4w; break;
        default: src = s4; hi = h4; lo = l4; n4 = n4w; break;
    }
    if (i >= n4) return;
    split_store(((const float4*)src)[i], hi, lo, i);
}

// NOTE: NOT volatile — register-only op; ptxas may interleave independent
// accumulator chains to hide HMMA latency. Each chain's own order (and thus
// the numerics) is preserved by the register dependences.
__device__ __forceinline__ void mma16816(float* c, const uint32_t* a,
                                         uint32_t b0, uint32_t b1) {
    asm("mma.sync.aligned.m16n8k16.row.col.f32.bf16.bf16.f32 "
        "{%0,%1,%2,%3}, {%4,%5,%6,%7}, {%8,%9}, {%0,%1,%2,%3};\n"
        : "+f"(c[0]), "+f"(c[1]), "+f"(c[2]), "+f"(c[3])
        : "r"(a[0]), "r"(a[1]), "r"(a[2]), "r"(a[3]), "r"(b0), "r"(b1));
}

__device__ __forceinline__ void ldm_x4(uint32_t* r, uint32_t addr) {
    asm volatile("ldmatrix.sync.aligned.m8n8.x4.shared.b16 {%0,%1,%2,%3}, [%4];"
        : "=r"(r[0]), "=r"(r[1]), "=r"(r[2]), "=r"(r[3]) : "r"(addr));
}

__device__ __forceinline__ void ldm_x4_t(uint32_t* r, uint32_t addr) {
    asm volatile("ldmatrix.sync.aligned.m8n8.x4.trans.shared.b16 {%0,%1,%2,%3}, [%4];"
        : "=r"(r[0]), "=r"(r[1]), "=r"(r[2]), "=r"(r[3]) : "r"(addr));
}

__device__ __forceinline__ void split2(float x, float y, uint32_t& hi, uint32_t& lo) {
    __nv_bfloat16 hx = __float2bfloat16(x), hy = __float2bfloat16(y);
    __nv_bfloat16 lx = __float2bfloat16(x - __bfloat162float(hx));
    __nv_bfloat16 ly = __float2bfloat16(y - __bfloat162float(hy));
    __nv_bfloat162 h(hx, hy), l(lx, ly);
    hi = *(uint32_t*)&h; lo = *(uint32_t*)&l;
}

// ---------------------------------------------------------------------------
// bf16-split HMMA GEMM: C = (Ahi+Alo)[M,K] @ (Bhi+Blo)[N,K]^T + bias
// CTA 128x128, BK=32, 8 warps. 3-stage cp.async ring with wait_group 1;
// swizzled 64B rows. 2 CTAs/SM. blockIdx.z selects weight set.
// MMAs interleaved across 4 independent accumulator chains (dist 4).
// ---------------------------------------------------------------------------
#define GBK      32
#define TILE_B   8192              // 128 rows * 64B (swizzled, no pad)
#define STAGE_B  (4 * TILE_B)      // 32768
#define NSTAGE   3
#define GEMM_SMEM (NSTAGE * STAGE_B)  // 98304

struct GemmBatch {
    const __nv_bfloat16* bh[3];
    const __nv_bfloat16* bl[3];
    const float* bias[3];
    __nv_bfloat16* ch[3];
    __nv_bfloat16* cl[3];
    float* cf[3];
};

__global__ __launch_bounds__(256, 2) void gemm_mma_kernel(
    const __nv_bfloat16* __restrict__ Ahi, const __nv_bfloat16* __restrict__ Alo,
    GemmBatch gb, int K)
{
    extern __shared__ char sm_raw[];
    int tid  = threadIdx.x;
    int lane = tid & 31, wid = tid >> 5;
    int g = lane >> 2;
    int q = lane & 3;
    int warpM = (wid & 3) * 32;
    int warpN = (wid >> 2) * 64;
    int n0 = blockIdx.x * 128;
    int m0 = blockIdx.y * 128;
    int z  = blockIdx.z;

    const __nv_bfloat16* Bhi = gb.bh[z];
    const __nv_bfloat16* Blo = gb.bl[z];
    const float* bias = gb.bias[z];
    __nv_bfloat16* Chi = gb.ch[z];
    __nv_bfloat16* Clo = gb.cl[z];
    float* Cf = gb.cf[z];

    uint32_t sbase = (uint32_t)__cvta_generic_to_shared(sm_raw);

    float acc[2][8][4] = {};
    const __nv_bfloat16* srcs[4] = {Ahi, Alo, Bhi, Blo};

    // 4 tiles of [128][32] bf16, 64B rows, swizzle: chunk ^= (row>>1)&3
    auto issue_loads = [&](int stage, int k0) {
        uint32_t st = sbase + stage * STAGE_B;
        int row4 = tid >> 2;      // 0..63
        int ch   = tid & 3;
        #pragma unroll
        for (int t = 0; t < 4; t++) {
            int rbase = (t < 2) ? m0 : n0;
            #pragma unroll
            for (int h = 0; h < 2; h++) {
                int row = row4 + h * 64;
                const void* gp = srcs[t] + (size_t)(rbase + row) * K + k0 + ch * 8;
                int sw = ch ^ ((row >> 1) & 3);
                uint32_t dp = st + t * TILE_B + row * 64 + sw * 16;
                asm volatile("cp.async.cg.shared.global [%0], [%1], 16;\n"
                             :: "r"(dp), "l"(gp));
            }
        }
        asm volatile("cp.async.commit_group;\n" ::: "memory");
    };

    auto compute = [&](int stage) {
        uint32_t st = sbase + stage * STAGE_B;
        uint32_t sA = st;               // Ahi; Alo at +TILE_B
        uint32_t sB = st + 2 * TILE_B;  // Bhi; Blo at +TILE_B
        int grp = lane >> 3;
        #pragma unroll
        for (int ks = 0; ks < GBK; ks += 16) {
            uint32_t ah[2][4], al[2][4];
            #pragma unroll
            for (int i = 0; i < 2; i++) {
                int ar = warpM + i * 16 + (lane & 15);
                int kc = (ks >> 3) + (lane >> 4);
                uint32_t ad = sA + (uint32_t)(ar * 64 + (kc ^ ((ar >> 1) & 3)) * 16);
                ldm_x4(ah[i], ad);
                ldm_x4(al[i], ad + TILE_B);
            }
            #pragma unroll
            for (int jp = 0; jp < 4; jp++) {
                int br = warpN + (jp * 2 + (grp >> 1)) * 8 + (lane & 7);
                int kc = (ks >> 3) + (grp & 1);
                uint32_t bd = sB + (uint32_t)(br * 64 + (kc ^ ((br >> 1) & 3)) * 16);
                uint32_t bh[4], bl[4];
                ldm_x4(bh, bd);
                ldm_x4(bl, bd + TILE_B);
                float* c00 = acc[0][jp * 2];
                float* c10 = acc[1][jp * 2];
                float* c01 = acc[0][jp * 2 + 1];
                float* c11 = acc[1][jp * 2 + 1];
                // pass-major over 4 independent chains (reuse distance 4)
                mma16816(c00, ah[0], bh[0], bh[1]);
                mma16816(c10, ah[1], bh[0], bh[1]);
                mma16816(c01, ah[0], bh[2], bh[3]);
                mma16816(c11, ah[1], bh[2], bh[3]);
                mma16816(c00, ah[0], bl[0], bl[1]);
                mma16816(c10, ah[1], bl[0], bl[1]);
                mma16816(c01, ah[0], bl[2], bl[3]);
                mma16816(c11, ah[1], bl[2], bl[3]);
                mma16816(c00, al[0], bh[0], bh[1]);
                mma16816(c10, al[1], bh[0], bh[1]);
                mma16816(c01, al[0], bh[2], bh[3]);
                mma16816(c11, al[1], bh[2], bh[3]);
            }
        }
    };

    const int NITER = K / GBK;    // 32
    issue_loads(0, 0);
    issue_loads(1, GBK);
    asm volatile("cp.async.wait_group 1;\n" ::: "memory");
    __syncthreads();
    for (int it = 0; it < NITER; it++) {
        if (it + 2 < NITER) {
            int nx = it + 2;
            int stg = nx - (nx / NSTAGE) * NSTAGE;
            issue_loads(stg, nx * GBK);
        }
        compute(it - (it / NSTAGE) * NSTAGE);
        if (it + 1 < NITER) {
            if (it + 2 < NITER) {
                asm volatile("cp.async.wait_group 1;\n" ::: "memory");
            } else {
                asm volatile("cp.async.wait_group 0;\n" ::: "memory");
            }
            __syncthreads();
        }
    }

    // --- epilogue ---
    #pragma unroll
    for (int i = 0; i < 2; i++) {
        int r0 = m0 + warpM + i * 16 + g;
        #pragma unroll
        for (int j = 0; j < 8; j++) {
            int c = n0 + warpN + j * 8 + q * 2;
            float2 b2 = *(const float2*)(bias + c);
            float o0 = acc[i][j][0] + b2.x, o1 = acc[i][j][1] + b2.y;
            float o2 = acc[i][j][2] + b2.x, o3 = acc[i][j][3] + b2.y;
            if (Cf) {
                *(float2*)(Cf + (size_t)r0 * DMODEL + c) = make_float2(o0, o1);
                *(float2*)(Cf + (size_t)(r0 + 8) * DMODEL + c) = make_float2(o2, o3);
            } else {
                uint32_t hp, lp;
                split2(o0, o1, hp, lp);
                *(uint32_t*)(Chi + (size_t)r0 * DMODEL + c) = hp;
                *(uint32_t*)(Clo + (size_t)r0 * DMODEL + c) = lp;
                split2(o2, o3, hp, lp);
                *(uint32_t*)(Chi + (size_t)(r0 + 8) * DMODEL + c) = hp;
                *(uint32_t*)(Clo + (size_t)(r0 + 8) * DMODEL + c) = lp;
            }
        }
    }
}

// ---------------------------------------------------------------------------
// HMMA flash attention, bf16 hi/lo split, causal.
// MMA chains interleaved (distance 2 + ptxas freedom from non-volatile mma).
// ---------------------------------------------------------------------------
#define AROW     144
#define QT_B     (128 * AROW)
#define KV_B     (64 * AROW)
#define KV_BASE  (2 * QT_B)
#define KVSTG_B  (4 * KV_B)
#define ATTN_SMEM (KV_BASE + 2 * KVSTG_B)  // 110592

__global__ __launch_bounds__(256, 2) void attn_mma_kernel(
    const __nv_bfloat16* __restrict__ Qhi, const __nv_bfloat16* __restrict__ Qlo,
    const __nv_bfloat16* __restrict__ Khi, const __nv_bfloat16* __restrict__ Klo,
    const __nv_bfloat16* __restrict__ Vhi, const __nv_bfloat16* __restrict__ Vlo,
    __nv_bfloat16* __restrict__ Ohi, __nv_bfloat16* __restrict__ Olo)
{
    extern __shared__ char sm_raw[];
    uint32_t sb = (uint32_t)__cvta_generic_to_shared(sm_raw);

    int tid  = threadIdx.x;
    int lane = tid & 31, w = tid >> 5;
    int g = lane >> 2, q = lane & 3;
    int head = blockIdx.y;
    int qb = (int)(gridDim.x - 1 - blockIdx.x);   // heavy tiles first
    int q0 = qb * 128;
    int col0 = head * DK;

    {
        const __nv_bfloat16* srcs[2] = {Qhi, Qlo};
        #pragma unroll
        for (int arr = 0; arr < 2; arr++)
            for (int c = tid; c < 1024; c += 256) {
                int row = c >> 3, ch = c & 7;
                const void* gp = srcs[arr] + (size_t)(q0 + row) * DMODEL + col0 + ch * 8;
                uint32_t dp = sb + arr * QT_B + row * AROW + ch * 16;
                asm volatile("cp.async.cg.shared.global [%0], [%1], 16;\n"
                             :: "r"(dp), "l"(gp));
            }
        asm volatile("cp.async.commit_group;\n" ::: "memory");
    }

    const __nv_bfloat16* kvsrc[4] = {Khi, Klo, Vhi, Vlo};
    auto issue_kv = [&](int kt, int stage) {
        int k0 = kt * 64;
        uint32_t st = sb + KV_BASE + stage * KVSTG_B;
        #pragma unroll
        for (int arr = 0; arr < 4; arr++)
            for (int c = tid; c < 512; c += 256) {
                int row = c >> 3, ch = c & 7;
                const void* gp = kvsrc[arr] + (size_t)(k0 + row) * DMODEL + col0 + ch * 8;
                uint32_t dp = st + arr * KV_B + row * AROW + ch * 16;
                asm volatile("cp.async.cg.shared.global [%0], [%1], 16;\n"
                             :: "r"(dp), "l"(gp));
            }
        asm volatile("cp.async.commit_group;\n" ::: "memory");
    };

    issue_kv(0, 0);
    asm volatile("cp.async.wait_group 0;\n" ::: "memory");
    __syncthreads();

    float o[8][4] = {};
    float m0r = -1e30f, m1r = -1e30f, l0r = 0.0f, l1r = 0.0f;
    const int r0 = q0 + w * 16;
    const int nt = 2 * qb + 2;
    int grp = lane >> 3;

    for (int kt = 0; kt < nt; kt++) {
        int k0 = kt * 64;
        if (kt + 1 < nt) issue_kv(kt + 1, (kt + 1) & 1);

        if (k0 <= r0 + 15) {
            uint32_t st  = sb + KV_BASE + (kt & 1) * KVSTG_B;
            uint32_t sQh = sb;
            uint32_t sKh = st;
            uint32_t sVh = st + 2 * KV_B;

            float s[8][4] = {};
            #pragma unroll
            for (int t = 0; t < 4; t++) {
                uint32_t qh[4], ql[4];
                uint32_t qa = sQh + (uint32_t)((w * 16 + (lane & 15)) * AROW
                                               + (t * 16 + (lane >> 4) * 8) * 2);
                ldm_x4(qh, qa);
                ldm_x4(ql, qa + QT_B);
                #pragma unroll
                for (int jp = 0; jp < 4; jp++) {
                    uint32_t bd = sKh + (uint32_t)(((jp * 2 + (grp >> 1)) * 8 + (lane & 7)) * AROW
                                                   + (t * 16 + (grp & 1) * 8) * 2);
                    uint32_t bh[4], bl[4];
                    ldm_x4(bh, bd);
                    ldm_x4(bl, bd + KV_B);
                    float* c0 = s[jp * 2];
                    float* c1 = s[jp * 2 + 1];
                    mma16816(c0, qh, bh[0], bh[1]);
                    mma16816(c1, qh, bh[2], bh[3]);
                    mma16816(c0, qh, bl[0], bl[1]);
                    mma16816(c1, qh, bl[2], bl[3]);
                    mma16816(c0, ql, bh[0], bh[1]);
                    mma16816(c1, ql, bh[2], bh[3]);
                }
            }

            bool need_mask = (k0 + 63 > r0);
            #pragma unroll
            for (int nb = 0; nb < 8; nb++)
                #pragma unroll
                for (int ci = 0; ci < 4; ci++) {
                    float v = s[nb][ci] * 0.125f;
                    if (need_mask) {
                        int row = r0 + g + (ci >> 1) * 8;
                        int key = k0 + nb * 8 + 2 * q + (ci & 1);
                        if (key > row) v = -1e30f;
                    }
                    s[nb][ci] = v;
                }

            float mx0 = -1e30f, mx1 = -1e30f;
            #pragma unroll
            for (int nb = 0; nb < 8; nb++) {
                mx0 = fmaxf(mx0, fmaxf(s[nb][0], s[nb][1]));
                mx1 = fmaxf(mx1, fmaxf(s[nb][2], s[nb][3]));
            }
            mx0 = fmaxf(mx0, __shfl_xor_sync(0xffffffffu, mx0, 1));
            mx0 = fmaxf(mx0, __shfl_xor_sync(0xffffffffu, mx0, 2));
            mx1 = fmaxf(mx1, __shfl_xor_sync(0xffffffffu, mx1, 1));
            mx1 = fmaxf(mx1, __shfl_xor_sync(0xffffffffu, mx1, 2));
            float mn0 = fmaxf(m0r, mx0), mn1 = fmaxf(m1r, mx1);
            float a0 = __expf(m0r - mn0), a1 = __expf(m1r - mn1);
            float ls0 = 0.0f, ls1 = 0.0f;
            #pragma unroll
            for (int nb = 0; nb < 8; nb++) {
                float p0 = __expf(s[nb][0] - mn0);
                float p1 = __expf(s[nb][1] - mn0);
                float p2 = __expf(s[nb][2] - mn1);
                float p3 = __expf(s[nb][3] - mn1);
                s[nb][0] = p0; s[nb][1] = p1; s[nb][2] = p2; s[nb][3] = p3;
                ls0 += p0 + p1; ls1 += p2 + p3;
            }
            ls0 += __shfl_xor_sync(0xffffffffu, ls0, 1);
            ls0 += __shfl_xor_sync(0xffffffffu, ls0, 2);
            ls1 += __shfl_xor_sync(0xffffffffu, ls1, 1);
            ls1 += __shfl_xor_sync(0xffffffffu, ls1, 2);
            l0r = l0r * a0 + ls0; l1r = l1r * a1 + ls1;
            m0r = mn0; m1r = mn1;
            #pragma unroll
            for (int nb = 0; nb < 8; nb++) {
                o[nb][0] *= a0; o[nb][1] *= a0;
                o[nb][2] *= a1; o[nb][3] *= a1;
            }

            #pragma unroll
            for (int t = 0; t < 4; t++) {
                uint32_t ph[4], pl[4];
                split2(s[2 * t][0],     s[2 * t][1],     ph[0], pl[0]);
                split2(s[2 * t][2],     s[2 * t][3],     ph[1], pl[1]);
                split2(s[2 * t + 1][0], s[2 * t + 1][1], ph[2], pl[2]);
                split2(s[2 * t + 1][2], s[2 * t + 1][3], ph[3], pl[3]);
                #pragma unroll
                for (int jp = 0; jp < 4; jp++) {
                    uint32_t vd = sVh + (uint32_t)((16 * t + (grp & 1) * 8 + (lane & 7)) * AROW
                                                   + ((jp * 2 + (grp >> 1)) * 8) * 2);
                    uint32_t vh[4], vl[4];
                    ldm_x4_t(vh, vd);
                    ldm_x4_t(vl, vd + KV_B);
                    float* c0 = o[jp * 2];
                    float* c1 = o[jp * 2 + 1];
                    mma16816(c0, ph, vh[0], vh[1]);
                    mma16816(c1, ph, vh[2], vh[3]);
                    mma16816(c0, ph, vl[0], vl[1]);
                    mma16816(c1, ph, vl[2], vl[3]);
                    mma16816(c0, pl, vh[0], vh[1]);
                    mma16816(c1, pl, vh[2], vh[3]);
                }
            }
        }

        if (kt + 1 < nt) {
            asm volatile("cp.async.wait_group 0;\n" ::: "memory");
            __syncthreads();
        }
    }

    float inv0 = 1.0f / l0r, inv1 = 1.0f / l1r;
    int row0 = q0 + w * 16 + g;
    int row1 = row0 + 8;
    #pragma unroll
    for (int nb = 0; nb < 8; nb++) {
        int c = col0 + nb * 8 + 2 * q;
        uint32_t hp, lp;
        split2(o[nb][0] * inv0, o[nb][1] * inv0, hp, lp);
        *(uint32_t*)(Ohi + (size_t)row0 * DMODEL + c) = hp;
        *(uint32_t*)(Olo + (size_t)row0 * DMODEL + c) = lp;
        split2(o[nb][2] * inv1, o[nb][3] * inv1, hp, lp);
        *(uint32_t*)(Ohi + (size_t)row1 * DMODEL + c) = hp;
        *(uint32_t*)(Olo + (size_t)row1 * DMODEL + c) = lp;
    }
}

// ---------------------------------------------------------------------------
extern "C" void kernel_launch(void* const* d_in, const int* in_sizes, int n_in,
                              void* d_out, int out_size)
{
    const float* x  = (const float*)d_in[0];
    const float* Wq = (const float*)d_in[1];
    const float* bq = (const float*)d_in[2];
    const float* Wk = (const float*)d_in[3];
    const float* bk = (const float*)d_in[4];
    const float* Wv = (const float*)d_in[5];
    const float* bv = (const float*)d_in[6];
    const float* Wo = (const float*)d_in[7];
    const float* bo = (const float*)d_in[8];
    float* out = (float*)d_out;

    __nv_bfloat16 *xhi, *xlo, *qhi, *qlo, *khi, *klo, *vhi, *vlo;
    __nv_bfloat16 *wqh, *wql, *wkh, *wkl, *wvh, *wvl, *woh, *wol;
    cudaGetSymbolAddress((void**)&xhi, g_xhi);
    cudaGetSymbolAddress((void**)&xlo, g_xlo);
    cudaGetSymbolAddress((void**)&qhi, g_qhi);
    cudaGetSymbolAddress((void**)&qlo, g_qlo);
    cudaGetSymbolAddress((void**)&khi, g_khi);
    cudaGetSymbolAddress((void**)&klo, g_klo);
    cudaGetSymbolAddress((void**)&vhi, g_vhi);
    cudaGetSymbolAddress((void**)&vlo, g_vlo);
    cudaGetSymbolAddress((void**)&wqh, g_wqhi);
    cudaGetSymbolAddress((void**)&wql, g_wqlo);
    cudaGetSymbolAddress((void**)&wkh, g_wkhi);
    cudaGetSymbolAddress((void**)&wkl, g_wklo);
    cudaGetSymbolAddress((void**)&wvh, g_wvhi);
    cudaGetSymbolAddress((void**)&wvl, g_wvlo);
    cudaGetSymbolAddress((void**)&woh, g_wohi);
    cudaGetSymbolAddress((void**)&wol, g_wolo);

    cudaFuncSetAttribute(gemm_mma_kernel,
                         cudaFuncAttributeMaxDynamicSharedMemorySize, GEMM_SMEM);
    cudaFuncSetAttribute(attn_mma_kernel,
                         cudaFuncAttributeMaxDynamicSharedMemorySize, ATTN_SMEM);

    const int NX4 = S_LEN * DMODEL / 4;    // 1,048,576 float4 (x)
    const int NW4 = DMODEL * DMODEL / 4;   //   262,144 float4 (each weight)

    cvt_split5_kernel<<<dim3((NX4 + 255) / 256, 5), 256>>>(
        x, Wq, Wk, Wv, Wo,
        xhi, wqh, wkh, wvh, woh,
        xlo, wql, wkl, wvl, wol, NX4, NW4);

    // fused Q/K/V projections: gridDim.z = 3 selects weight/output set
    GemmBatch qkv;
    qkv.bh[0] = wqh; qkv.bl[0] = wql; qkv.bias[0] = bq;
    qkv.ch[0] = qhi; qkv.cl[0] = qlo; qkv.cf[0] = nullptr;
    qkv.bh[1] = wkh; qkv.bl[1] = wkl; qkv.bias[1] = bk;
    qkv.ch[1] = khi; qkv.cl[1] = klo; qkv.cf[1] = nullptr;
    qkv.bh[2] = wvh; qkv.bl[2] = wvl; qkv.bias[2] = bv;
    qkv.ch[2] = vhi; qkv.cl[2] = vlo; qkv.cf[2] = nullptr;
    gemm_mma_kernel<<<dim3(DMODEL / 128, S_LEN / 128, 3), 256, GEMM_SMEM>>>(
        xhi, xlo, qkv, DMODEL);

    // attention writes its bf16 hi/lo output into xhi/xlo (x splits consumed)
    attn_mma_kernel<<<dim3(S_LEN / 128, NHEADS), 256, ATTN_SMEM>>>(
        qhi, qlo, khi, klo, vhi, vlo, xhi, xlo);

    // output projection (fp32 out)
    GemmBatch ob;
    ob.bh[0] = woh; ob.bl[0] = wol; ob.bias[0] = bo;
    ob.ch[0] = nullptr; ob.cl[0] = nullptr; ob.cf[0] = out;
    ob.bh[1] = ob.bh[0]; ob.bl[1] = ob.bl[0]; ob.bias[1] = ob.bias[0];
    ob.ch[1] = nullptr; ob.cl[1] = nullptr; ob.cf[1] = out;
    ob.bh[2] = ob.bh[0]; ob.bl[2] = ob.bl[0]; ob.bias[2] = ob.bias[0];
    ob.ch[2] = nullptr; ob.cl[2] = nullptr; ob.cf[2] = out;
    gemm_mma_kernel<<<dim3(DMODEL / 128, S_LEN / 128, 1), 256, GEMM_SMEM>>>(
        xhi, xlo, ob, DMODEL);
}